// round 12
// baseline (speedup 1.0000x reference)
#include <cuda_runtime.h>
#include <cuda_bf16.h>

// out[b,i,j] = softmax_j( exp( exp(-||x_bi - x_bj||^2 * p) ) ), B=128, K=1024.
//
// R12 = R10 with halved per-thread state to buy occupancy (latency-bound
// diagnosis: all pipes 52-60%, occ 46%; R11 showed neither MUFU nor fma
// throughput is binding).
//  - 512 threads / 16 warps, warp owns 64 columns (2 cols/lane), ROWS=8,
//    grid 16384 (same elements/block as R10 -> per-element load cost flat).
//  - v0[8]+v1[8]+float2 col regs ~ 40 regs -> __launch_bounds__(512,3)
//    = 48 warps/SM (occ ~72%, was 46%).
//  - SoA prep kernel, coalesced LDG.64 col loads, uniform LDG.128 row loads,
//    deferred butterfly (9 SHFL), STG.64.CS stores, 2x EX2 (pure MUFU path).

static constexpr int K = 1024;
static constexpr int B = 128;
static constexpr int BK = B * K;          // 131072 points
static constexpr int THREADS = 512;
static constexpr int ROWS = 8;
static constexpr float LOG2E = 1.4426950408889634f;
static constexpr float LOG2_LOG2E = 0.5287663729448977f;  // log2(log2(e))

// 8 x 512KB = 4MB scratch (static device arrays; no dynamic alloc).
__device__ __align__(16) float g_cx[BK];
__device__ __align__(16) float g_cy[BK];
__device__ __align__(16) float g_cz[BK];
__device__ __align__(16) float g_cw[BK];
__device__ __align__(16) float g_rx[BK];
__device__ __align__(16) float g_ry[BK];
__device__ __align__(16) float g_rz[BK];
__device__ __align__(16) float g_rw[BK];

__device__ __forceinline__ float ex2f(float x) {
    float r;
    asm("ex2.approx.f32 %0, %1;" : "=f"(r) : "f"(x));
    return r;
}

__global__ void __launch_bounds__(256)
prep_kernel(const float* __restrict__ coords, const float* __restrict__ prec)
{
    const int i = blockIdx.x * 256 + threadIdx.x;   // point index < BK
    const float q  = -prec[0] * LOG2E;
    const float s2 = -2.0f * q;

    const float x = coords[i * 3 + 0];
    const float y = coords[i * 3 + 1];
    const float z = coords[i * 3 + 2];
    const float nq = fmaf(x, x, fmaf(y, y, z * z)) * q;

    g_rx[i] = x;       g_ry[i] = y;       g_rz[i] = z;       g_rw[i] = nq;
    g_cx[i] = x * s2;  g_cy[i] = y * s2;  g_cz[i] = z * s2;  g_cw[i] = nq + LOG2_LOG2E;
}

__global__ void __launch_bounds__(THREADS, 3)
adjacency_softmax_kernel(float* __restrict__ out)
{
    __shared__ float wsum[ROWS][17];   // per-warp row sums (16 warps + pad)
    __shared__ float inv_s[ROWS];

    const int bq   = blockIdx.x >> 7;
    const int row0 = (blockIdx.x & 127) << 3;
    const int tid  = threadIdx.x;
    const int wid  = tid >> 5;
    const int lane = tid & 31;
    const int base = bq << 10;
    const int jb   = base + (wid << 6) + (lane << 1);   // 2 consecutive columns

    // ---- Column values: perfectly coalesced LDG.64 (2 wf each) ----
    const float2 cx = *reinterpret_cast<const float2*>(g_cx + jb);
    const float2 cy = *reinterpret_cast<const float2*>(g_cy + jb);
    const float2 cz = *reinterpret_cast<const float2*>(g_cz + jb);
    const float2 cw = *reinterpret_cast<const float2*>(g_cw + jb);

    float v0[ROWS], v1[ROWS];

    #pragma unroll
    for (int rc = 0; rc < ROWS / 4; rc++) {
        // Row values for 4 rows: uniform LDG.128 (1 wf each after first touch).
        const int rb = base + row0 + rc * 4;
        float rx[4], ry[4], rz[4], rw[4];
        *reinterpret_cast<float4*>(rx) = *reinterpret_cast<const float4*>(g_rx + rb);
        *reinterpret_cast<float4*>(ry) = *reinterpret_cast<const float4*>(g_ry + rb);
        *reinterpret_cast<float4*>(rz) = *reinterpret_cast<const float4*>(g_rz + rb);
        *reinterpret_cast<float4*>(rw) = *reinterpret_cast<const float4*>(g_rw + rb);

        #pragma unroll
        for (int r = 0; r < 4; r++) {
            const int vr = rc * 4 + r;
            const float ax = rx[r], ay = ry[r], az = rz[r], aw = rw[r];

            float t0 = aw + cw.x;
            float t1 = aw + cw.y;
            t0 = fmaf(ax, cx.x, t0);
            t1 = fmaf(ax, cx.y, t1);
            t0 = fmaf(ay, cy.x, t0);
            t1 = fmaf(ay, cy.y, t1);
            t0 = fmaf(az, cz.x, t0);
            t1 = fmaf(az, cz.y, t1);

            v0[vr] = ex2f(ex2f(t0));             // exp(exp(-d*p))
            v1[vr] = ex2f(ex2f(t1));
        }
    }

    // ---- Deferred cross-lane reduction: array-halving butterfly ----
    float s[ROWS];
    #pragma unroll
    for (int r = 0; r < ROWS; r++) s[r] = v0[r] + v1[r];

    #pragma unroll
    for (int stage = 0; stage < 3; stage++) {
        const int m = 1 << stage;        // xor mask: 1, 2, 4
        const int h = 4 >> stage;        // surviving half-size: 4, 2, 1
        const bool up = (lane & m) != 0;
        #pragma unroll
        for (int r = 0; r < h; r++) {
            const float x = up ? s[r + h] : s[r];
            const float y = up ? s[r]     : s[r + h];
            s[r] = x + __shfl_xor_sync(0xFFFFFFFFu, y, m);
        }
    }
    {
        float t = s[0];
        t += __shfl_xor_sync(0xFFFFFFFFu, t, 8);
        t += __shfl_xor_sync(0xFFFFFFFFu, t, 16);
        if (lane < 8) {
            const int row = ((lane & 1) << 2) | (lane & 2) | ((lane & 4) >> 2);
            wsum[row][wid] = t;
        }
    }
    __syncthreads();

    if (tid < ROWS) {
        float acc = 0.0f;
        #pragma unroll
        for (int w = 0; w < 16; w++) acc += wsum[tid][w];
        inv_s[tid] = __fdividef(1.0f, acc);
    }
    __syncthreads();

    float* __restrict__ ob =
        out + ((size_t)bq * K + row0) * K + (jb - base);

    #pragma unroll
    for (int r = 0; r < ROWS; r++) {
        const float inv = inv_s[r];
        const float2 res = make_float2(v0[r] * inv, v1[r] * inv);
        __stcs(reinterpret_cast<float2*>(ob + (size_t)r * K), res);  // STG.64.CS
    }
}

extern "C" void kernel_launch(void* const* d_in, const int* in_sizes, int n_in,
                              void* d_out, int out_size)
{
    const float* coords = (const float*)d_in[0];   // [128, 1024, 3] f32
    const float* prec   = (const float*)d_in[1];   // [1] f32
    float* out          = (float*)d_out;           // [128, 1024, 1024] f32

    prep_kernel<<<BK / 256, 256>>>(coords, prec);
    dim3 grid(B * (K / ROWS));   // 16384 blocks
    adjacency_softmax_kernel<<<grid, THREADS>>>(out);
}

// round 13
// speedup vs baseline: 1.2178x; 1.2178x over previous
#include <cuda_runtime.h>
#include <cuda_bf16.h>

// out[b,i,j] = softmax_j( exp( exp(-||x_bi - x_bj||^2 * p) ) ), B=128, K=1024.
//
// R13 = R10 (best, 94.7us) with ONE change: plain STG.128 instead of
// __stcs. With 126MB L2, default write policy buffers stores in L2 and
// drains asynchronously; .cs evict-first may throttle burst absorption.
// Single-variable cache-policy experiment on the store path.
//  - SoA prep kernel (coords -> 8 prescaled arrays, 4MB static scratch).
//  - 256 thr / 8 warps / 8 rows per block, 4 consecutive cols per lane,
//    coalesced LDG.128 col loads, uniform LDG.128 row loads,
//    deferred butterfly (9 SHFL), STG.128 stores, grid 16384.

static constexpr int K = 1024;
static constexpr int B = 128;
static constexpr int BK = B * K;          // 131072 points
static constexpr int THREADS = 256;
static constexpr int ROWS = 8;
static constexpr float LOG2E = 1.4426950408889634f;
static constexpr float LOG2_LOG2E = 0.5287663729448977f;  // log2(log2(e))

// 8 x 512KB = 4MB scratch (static device arrays; no dynamic alloc).
__device__ __align__(16) float g_cx[BK];
__device__ __align__(16) float g_cy[BK];
__device__ __align__(16) float g_cz[BK];
__device__ __align__(16) float g_cw[BK];
__device__ __align__(16) float g_rx[BK];
__device__ __align__(16) float g_ry[BK];
__device__ __align__(16) float g_rz[BK];
__device__ __align__(16) float g_rw[BK];

__device__ __forceinline__ float ex2f(float x) {
    float r;
    asm("ex2.approx.f32 %0, %1;" : "=f"(r) : "f"(x));
    return r;
}

__global__ void __launch_bounds__(256)
prep_kernel(const float* __restrict__ coords, const float* __restrict__ prec)
{
    const int i = blockIdx.x * 256 + threadIdx.x;   // point index < BK
    const float q  = -prec[0] * LOG2E;
    const float s2 = -2.0f * q;

    const float x = coords[i * 3 + 0];
    const float y = coords[i * 3 + 1];
    const float z = coords[i * 3 + 2];
    const float nq = fmaf(x, x, fmaf(y, y, z * z)) * q;

    g_rx[i] = x;       g_ry[i] = y;       g_rz[i] = z;       g_rw[i] = nq;
    g_cx[i] = x * s2;  g_cy[i] = y * s2;  g_cz[i] = z * s2;  g_cw[i] = nq + LOG2_LOG2E;
}

__global__ void __launch_bounds__(THREADS, 4)
adjacency_softmax_kernel(float* __restrict__ out)
{
    __shared__ float wsum[ROWS][9];    // per-warp row sums (padded)
    __shared__ float inv_s[ROWS];

    const int bq   = blockIdx.x >> 7;
    const int row0 = (blockIdx.x & 127) << 3;
    const int tid  = threadIdx.x;
    const int wid  = tid >> 5;
    const int lane = tid & 31;
    const int base = bq << 10;
    const int jb   = base + (wid << 7) + (lane << 2);   // 4 consecutive columns

    // ---- Column values: perfectly coalesced LDG.128 (4 wf each) ----
    const float4 cx = *reinterpret_cast<const float4*>(g_cx + jb);
    const float4 cy = *reinterpret_cast<const float4*>(g_cy + jb);
    const float4 cz = *reinterpret_cast<const float4*>(g_cz + jb);
    const float4 cw = *reinterpret_cast<const float4*>(g_cw + jb);

    float v0[ROWS], v1[ROWS], v2[ROWS], v3[ROWS];

    #pragma unroll
    for (int rc = 0; rc < ROWS / 4; rc++) {
        // Row values for 4 rows: uniform LDG.128 (1 wf each after first touch).
        const int rb = base + row0 + rc * 4;
        float rx[4], ry[4], rz[4], rw[4];
        *reinterpret_cast<float4*>(rx) = *reinterpret_cast<const float4*>(g_rx + rb);
        *reinterpret_cast<float4*>(ry) = *reinterpret_cast<const float4*>(g_ry + rb);
        *reinterpret_cast<float4*>(rz) = *reinterpret_cast<const float4*>(g_rz + rb);
        *reinterpret_cast<float4*>(rw) = *reinterpret_cast<const float4*>(g_rw + rb);

        #pragma unroll
        for (int r = 0; r < 4; r++) {
            const int vr = rc * 4 + r;
            const float ax = rx[r], ay = ry[r], az = rz[r], aw = rw[r];

            float t0 = aw + cw.x;
            float t1 = aw + cw.y;
            float t2 = aw + cw.z;
            float t3 = aw + cw.w;
            t0 = fmaf(ax, cx.x, t0);
            t1 = fmaf(ax, cx.y, t1);
            t2 = fmaf(ax, cx.z, t2);
            t3 = fmaf(ax, cx.w, t3);
            t0 = fmaf(ay, cy.x, t0);
            t1 = fmaf(ay, cy.y, t1);
            t2 = fmaf(ay, cy.z, t2);
            t3 = fmaf(ay, cy.w, t3);
            t0 = fmaf(az, cz.x, t0);
            t1 = fmaf(az, cz.y, t1);
            t2 = fmaf(az, cz.z, t2);
            t3 = fmaf(az, cz.w, t3);

            v0[vr] = ex2f(ex2f(t0));             // exp(exp(-d*p))
            v1[vr] = ex2f(ex2f(t1));
            v2[vr] = ex2f(ex2f(t2));
            v3[vr] = ex2f(ex2f(t3));
        }
    }

    // ---- Deferred cross-lane reduction: array-halving butterfly ----
    float s[ROWS];
    #pragma unroll
    for (int r = 0; r < ROWS; r++)
        s[r] = (v0[r] + v1[r]) + (v2[r] + v3[r]);

    #pragma unroll
    for (int stage = 0; stage < 3; stage++) {
        const int m = 1 << stage;        // xor mask: 1, 2, 4
        const int h = 4 >> stage;        // surviving half-size: 4, 2, 1
        const bool up = (lane & m) != 0;
        #pragma unroll
        for (int r = 0; r < h; r++) {
            const float x = up ? s[r + h] : s[r];
            const float y = up ? s[r]     : s[r + h];
            s[r] = x + __shfl_xor_sync(0xFFFFFFFFu, y, m);
        }
    }
    {
        float t = s[0];
        t += __shfl_xor_sync(0xFFFFFFFFu, t, 8);
        t += __shfl_xor_sync(0xFFFFFFFFu, t, 16);
        if (lane < 8) {
            const int row = ((lane & 1) << 2) | (lane & 2) | ((lane & 4) >> 2);
            wsum[row][wid] = t;
        }
    }
    __syncthreads();

    if (tid < ROWS) {
        float acc = 0.0f;
        #pragma unroll
        for (int w = 0; w < 8; w++) acc += wsum[tid][w];
        inv_s[tid] = __fdividef(1.0f, acc);
    }
    __syncthreads();

    float* __restrict__ ob =
        out + ((size_t)bq * K + row0) * K + (jb - base);

    #pragma unroll
    for (int r = 0; r < ROWS; r++) {
        const float inv = inv_s[r];
        const float4 res = make_float4(v0[r] * inv, v1[r] * inv,
                                       v2[r] * inv, v3[r] * inv);
        *reinterpret_cast<float4*>(ob + (size_t)r * K) = res;   // STG.128 (default policy)
    }
}

extern "C" void kernel_launch(void* const* d_in, const int* in_sizes, int n_in,
                              void* d_out, int out_size)
{
    const float* coords = (const float*)d_in[0];   // [128, 1024, 3] f32
    const float* prec   = (const float*)d_in[1];   // [1] f32
    float* out          = (float*)d_out;           // [128, 1024, 1024] f32

    prep_kernel<<<BK / 256, 256>>>(coords, prec);
    dim3 grid(B * (K / ROWS));   // 16384 blocks
    adjacency_softmax_kernel<<<grid, THREADS>>>(out);
}

// round 14
// speedup vs baseline: 1.3367x; 1.0976x over previous
#include <cuda_runtime.h>
#include <cuda_bf16.h>

// out[b,i,j] = softmax_j( exp( exp(-||x_bi - x_bj||^2 * p) ) ), B=128, K=1024.
//
// R14 = R10 (best, 94.7us; __stcs confirmed +12us vs default in R13) with
// one subtractive tweak: the raw-row scratch arrays g_r* are removed; row
// values are derived from the prescaled column arrays (ax = cx/s2,
// aw = cw - log2(log2e)) at ~5 extra flops per 4 rows. Halves prep work and
// makes row loads hit the same L2-hot lines as column loads.
//  - 256 thr / 8 warps / 8 rows per block, 4 consecutive cols per lane,
//    coalesced LDG.128 col loads, uniform LDG.128 row loads,
//    deferred butterfly (9 SHFL), STG.128.CS, grid 16384.

static constexpr int K = 1024;
static constexpr int B = 128;
static constexpr int BK = B * K;          // 131072 points
static constexpr int THREADS = 256;
static constexpr int ROWS = 8;
static constexpr float LOG2E = 1.4426950408889634f;
static constexpr float LOG2_LOG2E = 0.5287663729448977f;  // log2(log2(e))

// 4 x 512KB = 2MB scratch (static device arrays; no dynamic alloc).
__device__ __align__(16) float g_cx[BK];
__device__ __align__(16) float g_cy[BK];
__device__ __align__(16) float g_cz[BK];
__device__ __align__(16) float g_cw[BK];

__device__ __forceinline__ float ex2f(float x) {
    float r;
    asm("ex2.approx.f32 %0, %1;" : "=f"(r) : "f"(x));
    return r;
}

__global__ void __launch_bounds__(256)
prep_kernel(const float* __restrict__ coords, const float* __restrict__ prec)
{
    const int i = blockIdx.x * 256 + threadIdx.x;   // point index < BK
    const float q  = -prec[0] * LOG2E;
    const float s2 = -2.0f * q;

    const float x = coords[i * 3 + 0];
    const float y = coords[i * 3 + 1];
    const float z = coords[i * 3 + 2];
    const float nq = fmaf(x, x, fmaf(y, y, z * z)) * q;

    g_cx[i] = x * s2;  g_cy[i] = y * s2;  g_cz[i] = z * s2;
    g_cw[i] = nq + LOG2_LOG2E;
}

__global__ void __launch_bounds__(THREADS, 4)
adjacency_softmax_kernel(float* __restrict__ out, const float* __restrict__ prec)
{
    __shared__ float wsum[ROWS][9];    // per-warp row sums (padded)
    __shared__ float inv_s[ROWS];

    const int bq   = blockIdx.x >> 7;
    const int row0 = (blockIdx.x & 127) << 3;
    const int tid  = threadIdx.x;
    const int wid  = tid >> 5;
    const int lane = tid & 31;
    const int base = bq << 10;
    const int jb   = base + (wid << 7) + (lane << 2);   // 4 consecutive columns

    // inverse of s2 = 2*p*log2e, to recover raw coords from prescaled ones
    const float inv_s2 = __fdividef(0.5f / LOG2E, prec[0]);

    // ---- Column values: perfectly coalesced LDG.128 (4 wf each) ----
    const float4 cx = *reinterpret_cast<const float4*>(g_cx + jb);
    const float4 cy = *reinterpret_cast<const float4*>(g_cy + jb);
    const float4 cz = *reinterpret_cast<const float4*>(g_cz + jb);
    const float4 cw = *reinterpret_cast<const float4*>(g_cw + jb);

    float v0[ROWS], v1[ROWS], v2[ROWS], v3[ROWS];

    #pragma unroll
    for (int rc = 0; rc < ROWS / 4; rc++) {
        // Row values for 4 rows: uniform LDG.128 of the SAME L2-hot arrays,
        // un-scaled on the fly (ax = cx * 1/s2, aw = cw - log2log2e).
        const int rb = base + row0 + rc * 4;
        float rx[4], ry[4], rz[4], rw[4];
        *reinterpret_cast<float4*>(rx) = *reinterpret_cast<const float4*>(g_cx + rb);
        *reinterpret_cast<float4*>(ry) = *reinterpret_cast<const float4*>(g_cy + rb);
        *reinterpret_cast<float4*>(rz) = *reinterpret_cast<const float4*>(g_cz + rb);
        *reinterpret_cast<float4*>(rw) = *reinterpret_cast<const float4*>(g_cw + rb);

        #pragma unroll
        for (int r = 0; r < 4; r++) {
            const int vr = rc * 4 + r;
            const float ax = rx[r] * inv_s2;
            const float ay = ry[r] * inv_s2;
            const float az = rz[r] * inv_s2;
            const float aw = rw[r] - LOG2_LOG2E;

            float t0 = aw + cw.x;
            float t1 = aw + cw.y;
            float t2 = aw + cw.z;
            float t3 = aw + cw.w;
            t0 = fmaf(ax, cx.x, t0);
            t1 = fmaf(ax, cx.y, t1);
            t2 = fmaf(ax, cx.z, t2);
            t3 = fmaf(ax, cx.w, t3);
            t0 = fmaf(ay, cy.x, t0);
            t1 = fmaf(ay, cy.y, t1);
            t2 = fmaf(ay, cy.z, t2);
            t3 = fmaf(ay, cy.w, t3);
            t0 = fmaf(az, cz.x, t0);
            t1 = fmaf(az, cz.y, t1);
            t2 = fmaf(az, cz.z, t2);
            t3 = fmaf(az, cz.w, t3);

            v0[vr] = ex2f(ex2f(t0));             // exp(exp(-d*p))
            v1[vr] = ex2f(ex2f(t1));
            v2[vr] = ex2f(ex2f(t2));
            v3[vr] = ex2f(ex2f(t3));
        }
    }

    // ---- Deferred cross-lane reduction: array-halving butterfly ----
    float s[ROWS];
    #pragma unroll
    for (int r = 0; r < ROWS; r++)
        s[r] = (v0[r] + v1[r]) + (v2[r] + v3[r]);

    #pragma unroll
    for (int stage = 0; stage < 3; stage++) {
        const int m = 1 << stage;        // xor mask: 1, 2, 4
        const int h = 4 >> stage;        // surviving half-size: 4, 2, 1
        const bool up = (lane & m) != 0;
        #pragma unroll
        for (int r = 0; r < h; r++) {
            const float x = up ? s[r + h] : s[r];
            const float y = up ? s[r]     : s[r + h];
            s[r] = x + __shfl_xor_sync(0xFFFFFFFFu, y, m);
        }
    }
    {
        float t = s[0];
        t += __shfl_xor_sync(0xFFFFFFFFu, t, 8);
        t += __shfl_xor_sync(0xFFFFFFFFu, t, 16);
        if (lane < 8) {
            const int row = ((lane & 1) << 2) | (lane & 2) | ((lane & 4) >> 2);
            wsum[row][wid] = t;
        }
    }
    __syncthreads();

    if (tid < ROWS) {
        float acc = 0.0f;
        #pragma unroll
        for (int w = 0; w < 8; w++) acc += wsum[tid][w];
        inv_s[tid] = __fdividef(1.0f, acc);
    }
    __syncthreads();

    float* __restrict__ ob =
        out + ((size_t)bq * K + row0) * K + (jb - base);

    #pragma unroll
    for (int r = 0; r < ROWS; r++) {
        const float inv = inv_s[r];
        const float4 res = make_float4(v0[r] * inv, v1[r] * inv,
                                       v2[r] * inv, v3[r] * inv);
        __stcs(reinterpret_cast<float4*>(ob + (size_t)r * K), res);  // STG.128.CS
    }
}

extern "C" void kernel_launch(void* const* d_in, const int* in_sizes, int n_in,
                              void* d_out, int out_size)
{
    const float* coords = (const float*)d_in[0];   // [128, 1024, 3] f32
    const float* prec   = (const float*)d_in[1];   // [1] f32
    float* out          = (float*)d_out;           // [128, 1024, 1024] f32

    prep_kernel<<<BK / 256, 256>>>(coords, prec);
    dim3 grid(B * (K / ROWS));   // 16384 blocks
    adjacency_softmax_kernel<<<grid, THREADS>>>(out, prec);
}

// round 15
// speedup vs baseline: 1.3483x; 1.0086x over previous
#include <cuda_runtime.h>
#include <cuda_bf16.h>

// out[b,i,j] = softmax_j( exp( exp(-||x_bi - x_bj||^2 * p) ) ), B=128, K=1024.
//
// R15 = R10 restored byte-for-byte (best: 94.7us) + max-L1 carveout hint.
// R14's on-the-fly row unscaling cost ~2us of hot-loop fma/alu — reverted.
// R13 proved __stcs is +12us vs default — kept.
//  - SoA prep kernel: coords -> 8 prescaled arrays (4MB static scratch).
//  - 256 thr / 8 warps / 8 rows per block, 4 consecutive cols per lane,
//    coalesced LDG.128 col loads, uniform LDG.128 row loads,
//    deferred butterfly (9 SHFL), STG.128.CS, grid 16384.
//  - PreferredSharedMemoryCarveout=0 (kernel uses 320B smem): full 228KB
//    unified cache to L1D for the SoA scratch + row-broadcast lines.

static constexpr int K = 1024;
static constexpr int B = 128;
static constexpr int BK = B * K;          // 131072 points
static constexpr int THREADS = 256;
static constexpr int ROWS = 8;
static constexpr float LOG2E = 1.4426950408889634f;
static constexpr float LOG2_LOG2E = 0.5287663729448977f;  // log2(log2(e))

// 8 x 512KB = 4MB scratch (static device arrays; no dynamic alloc).
__device__ __align__(16) float g_cx[BK];
__device__ __align__(16) float g_cy[BK];
__device__ __align__(16) float g_cz[BK];
__device__ __align__(16) float g_cw[BK];
__device__ __align__(16) float g_rx[BK];
__device__ __align__(16) float g_ry[BK];
__device__ __align__(16) float g_rz[BK];
__device__ __align__(16) float g_rw[BK];

__device__ __forceinline__ float ex2f(float x) {
    float r;
    asm("ex2.approx.f32 %0, %1;" : "=f"(r) : "f"(x));
    return r;
}

__global__ void __launch_bounds__(256)
prep_kernel(const float* __restrict__ coords, const float* __restrict__ prec)
{
    const int i = blockIdx.x * 256 + threadIdx.x;   // point index < BK
    const float q  = -prec[0] * LOG2E;
    const float s2 = -2.0f * q;

    const float x = coords[i * 3 + 0];
    const float y = coords[i * 3 + 1];
    const float z = coords[i * 3 + 2];
    const float nq = fmaf(x, x, fmaf(y, y, z * z)) * q;

    g_rx[i] = x;       g_ry[i] = y;       g_rz[i] = z;       g_rw[i] = nq;
    g_cx[i] = x * s2;  g_cy[i] = y * s2;  g_cz[i] = z * s2;  g_cw[i] = nq + LOG2_LOG2E;
}

__global__ void __launch_bounds__(THREADS, 4)
adjacency_softmax_kernel(float* __restrict__ out)
{
    __shared__ float wsum[ROWS][9];    // per-warp row sums (padded)
    __shared__ float inv_s[ROWS];

    const int bq   = blockIdx.x >> 7;
    const int row0 = (blockIdx.x & 127) << 3;
    const int tid  = threadIdx.x;
    const int wid  = tid >> 5;
    const int lane = tid & 31;
    const int base = bq << 10;
    const int jb   = base + (wid << 7) + (lane << 2);   // 4 consecutive columns

    // ---- Column values: perfectly coalesced LDG.128 (4 wf each) ----
    const float4 cx = *reinterpret_cast<const float4*>(g_cx + jb);
    const float4 cy = *reinterpret_cast<const float4*>(g_cy + jb);
    const float4 cz = *reinterpret_cast<const float4*>(g_cz + jb);
    const float4 cw = *reinterpret_cast<const float4*>(g_cw + jb);

    float v0[ROWS], v1[ROWS], v2[ROWS], v3[ROWS];

    #pragma unroll
    for (int rc = 0; rc < ROWS / 4; rc++) {
        // Row values for 4 rows: uniform LDG.128 (1 wf each after first touch).
        const int rb = base + row0 + rc * 4;
        float rx[4], ry[4], rz[4], rw[4];
        *reinterpret_cast<float4*>(rx) = *reinterpret_cast<const float4*>(g_rx + rb);
        *reinterpret_cast<float4*>(ry) = *reinterpret_cast<const float4*>(g_ry + rb);
        *reinterpret_cast<float4*>(rz) = *reinterpret_cast<const float4*>(g_rz + rb);
        *reinterpret_cast<float4*>(rw) = *reinterpret_cast<const float4*>(g_rw + rb);

        #pragma unroll
        for (int r = 0; r < 4; r++) {
            const int vr = rc * 4 + r;
            const float ax = rx[r], ay = ry[r], az = rz[r], aw = rw[r];

            float t0 = aw + cw.x;
            float t1 = aw + cw.y;
            float t2 = aw + cw.z;
            float t3 = aw + cw.w;
            t0 = fmaf(ax, cx.x, t0);
            t1 = fmaf(ax, cx.y, t1);
            t2 = fmaf(ax, cx.z, t2);
            t3 = fmaf(ax, cx.w, t3);
            t0 = fmaf(ay, cy.x, t0);
            t1 = fmaf(ay, cy.y, t1);
            t2 = fmaf(ay, cy.z, t2);
            t3 = fmaf(ay, cy.w, t3);
            t0 = fmaf(az, cz.x, t0);
            t1 = fmaf(az, cz.y, t1);
            t2 = fmaf(az, cz.z, t2);
            t3 = fmaf(az, cz.w, t3);

            v0[vr] = ex2f(ex2f(t0));             // exp(exp(-d*p))
            v1[vr] = ex2f(ex2f(t1));
            v2[vr] = ex2f(ex2f(t2));
            v3[vr] = ex2f(ex2f(t3));
        }
    }

    // ---- Deferred cross-lane reduction: array-halving butterfly ----
    float s[ROWS];
    #pragma unroll
    for (int r = 0; r < ROWS; r++)
        s[r] = (v0[r] + v1[r]) + (v2[r] + v3[r]);

    #pragma unroll
    for (int stage = 0; stage < 3; stage++) {
        const int m = 1 << stage;        // xor mask: 1, 2, 4
        const int h = 4 >> stage;        // surviving half-size: 4, 2, 1
        const bool up = (lane & m) != 0;
        #pragma unroll
        for (int r = 0; r < h; r++) {
            const float x = up ? s[r + h] : s[r];
            const float y = up ? s[r]     : s[r + h];
            s[r] = x + __shfl_xor_sync(0xFFFFFFFFu, y, m);
        }
    }
    {
        float t = s[0];
        t += __shfl_xor_sync(0xFFFFFFFFu, t, 8);
        t += __shfl_xor_sync(0xFFFFFFFFu, t, 16);
        if (lane < 8) {
            const int row = ((lane & 1) << 2) | (lane & 2) | ((lane & 4) >> 2);
            wsum[row][wid] = t;
        }
    }
    __syncthreads();

    if (tid < ROWS) {
        float acc = 0.0f;
        #pragma unroll
        for (int w = 0; w < 8; w++) acc += wsum[tid][w];
        inv_s[tid] = __fdividef(1.0f, acc);
    }
    __syncthreads();

    float* __restrict__ ob =
        out + ((size_t)bq * K + row0) * K + (jb - base);

    #pragma unroll
    for (int r = 0; r < ROWS; r++) {
        const float inv = inv_s[r];
        const float4 res = make_float4(v0[r] * inv, v1[r] * inv,
                                       v2[r] * inv, v3[r] * inv);
        __stcs(reinterpret_cast<float4*>(ob + (size_t)r * K), res);  // STG.128.CS
    }
}

extern "C" void kernel_launch(void* const* d_in, const int* in_sizes, int n_in,
                              void* d_out, int out_size)
{
    const float* coords = (const float*)d_in[0];   // [128, 1024, 3] f32
    const float* prec   = (const float*)d_in[1];   // [1] f32
    float* out          = (float*)d_out;           // [128, 1024, 1024] f32

    // Max-L1 carveout: kernels use <1KB smem; give the unified cache to L1D.
    // Idempotent attribute set; not a stream op; graph-capture-safe; no alloc.
    cudaFuncSetAttribute(adjacency_softmax_kernel,
                         cudaFuncAttributePreferredSharedMemoryCarveout, 0);

    prep_kernel<<<BK / 256, 256>>>(coords, prec);
    dim3 grid(B * (K / ROWS));   // 16384 blocks
    adjacency_softmax_kernel<<<grid, THREADS>>>(out);
}

// round 16
// speedup vs baseline: 1.3524x; 1.0030x over previous
#include <cuda_runtime.h>
#include <cuda_bf16.h>

// out[b,i,j] = softmax_j( exp( exp(-||x_bi - x_bj||^2 * p) ) ), B=128, K=1024.
//
// R16 = R10 (best, 94.7us) + PDL overlap of the prep->main launch bubble.
//  - prep kernel triggers programmatic launch completion right after its
//    stores; main kernel runs its prologue concurrently and gates the first
//    scratch read with cudaGridDependencySynchronize().
//  - Kernel bodies otherwise identical to R10: SoA prep (8 prescaled arrays,
//    4MB static scratch), 256 thr / 8 warps / 8 rows / 4 cols per lane,
//    coalesced LDG.128, deferred butterfly (9 SHFL), STG.128.CS, grid 16384.

static constexpr int K = 1024;
static constexpr int B = 128;
static constexpr int BK = B * K;          // 131072 points
static constexpr int THREADS = 256;
static constexpr int ROWS = 8;
static constexpr float LOG2E = 1.4426950408889634f;
static constexpr float LOG2_LOG2E = 0.5287663729448977f;  // log2(log2(e))

// 8 x 512KB = 4MB scratch (static device arrays; no dynamic alloc).
__device__ __align__(16) float g_cx[BK];
__device__ __align__(16) float g_cy[BK];
__device__ __align__(16) float g_cz[BK];
__device__ __align__(16) float g_cw[BK];
__device__ __align__(16) float g_rx[BK];
__device__ __align__(16) float g_ry[BK];
__device__ __align__(16) float g_rz[BK];
__device__ __align__(16) float g_rw[BK];

__device__ __forceinline__ float ex2f(float x) {
    float r;
    asm("ex2.approx.f32 %0, %1;" : "=f"(r) : "f"(x));
    return r;
}

__global__ void __launch_bounds__(256)
prep_kernel(const float* __restrict__ coords, const float* __restrict__ prec)
{
    const int i = blockIdx.x * 256 + threadIdx.x;   // point index < BK
    const float q  = -prec[0] * LOG2E;
    const float s2 = -2.0f * q;

    const float x = coords[i * 3 + 0];
    const float y = coords[i * 3 + 1];
    const float z = coords[i * 3 + 2];
    const float nq = fmaf(x, x, fmaf(y, y, z * z)) * q;

    g_rx[i] = x;       g_ry[i] = y;       g_rz[i] = z;       g_rw[i] = nq;
    g_cx[i] = x * s2;  g_cy[i] = y * s2;  g_cz[i] = z * s2;  g_cw[i] = nq + LOG2_LOG2E;

#if __CUDA_ARCH__ >= 900
    cudaTriggerProgrammaticLaunchCompletion();
#endif
}

__global__ void __launch_bounds__(THREADS, 4)
adjacency_softmax_kernel(float* __restrict__ out)
{
    __shared__ float wsum[ROWS][9];    // per-warp row sums (padded)
    __shared__ float inv_s[ROWS];

    // ---- Prologue: pure index math, overlapped with prep via PDL ----
    const int bq   = blockIdx.x >> 7;
    const int row0 = (blockIdx.x & 127) << 3;
    const int tid  = threadIdx.x;
    const int wid  = tid >> 5;
    const int lane = tid & 31;
    const int base = bq << 10;
    const int jb   = base + (wid << 7) + (lane << 2);   // 4 consecutive columns

#if __CUDA_ARCH__ >= 900
    cudaGridDependencySynchronize();   // wait for prep's scratch to be valid
#endif

    // ---- Column values: perfectly coalesced LDG.128 (4 wf each) ----
    const float4 cx = *reinterpret_cast<const float4*>(g_cx + jb);
    const float4 cy = *reinterpret_cast<const float4*>(g_cy + jb);
    const float4 cz = *reinterpret_cast<const float4*>(g_cz + jb);
    const float4 cw = *reinterpret_cast<const float4*>(g_cw + jb);

    float v0[ROWS], v1[ROWS], v2[ROWS], v3[ROWS];

    #pragma unroll
    for (int rc = 0; rc < ROWS / 4; rc++) {
        // Row values for 4 rows: uniform LDG.128 (1 wf each after first touch).
        const int rb = base + row0 + rc * 4;
        float rx[4], ry[4], rz[4], rw[4];
        *reinterpret_cast<float4*>(rx) = *reinterpret_cast<const float4*>(g_rx + rb);
        *reinterpret_cast<float4*>(ry) = *reinterpret_cast<const float4*>(g_ry + rb);
        *reinterpret_cast<float4*>(rz) = *reinterpret_cast<const float4*>(g_rz + rb);
        *reinterpret_cast<float4*>(rw) = *reinterpret_cast<const float4*>(g_rw + rb);

        #pragma unroll
        for (int r = 0; r < 4; r++) {
            const int vr = rc * 4 + r;
            const float ax = rx[r], ay = ry[r], az = rz[r], aw = rw[r];

            float t0 = aw + cw.x;
            float t1 = aw + cw.y;
            float t2 = aw + cw.z;
            float t3 = aw + cw.w;
            t0 = fmaf(ax, cx.x, t0);
            t1 = fmaf(ax, cx.y, t1);
            t2 = fmaf(ax, cx.z, t2);
            t3 = fmaf(ax, cx.w, t3);
            t0 = fmaf(ay, cy.x, t0);
            t1 = fmaf(ay, cy.y, t1);
            t2 = fmaf(ay, cy.z, t2);
            t3 = fmaf(ay, cy.w, t3);
            t0 = fmaf(az, cz.x, t0);
            t1 = fmaf(az, cz.y, t1);
            t2 = fmaf(az, cz.z, t2);
            t3 = fmaf(az, cz.w, t3);

            v0[vr] = ex2f(ex2f(t0));             // exp(exp(-d*p))
            v1[vr] = ex2f(ex2f(t1));
            v2[vr] = ex2f(ex2f(t2));
            v3[vr] = ex2f(ex2f(t3));
        }
    }

    // ---- Deferred cross-lane reduction: array-halving butterfly ----
    float s[ROWS];
    #pragma unroll
    for (int r = 0; r < ROWS; r++)
        s[r] = (v0[r] + v1[r]) + (v2[r] + v3[r]);

    #pragma unroll
    for (int stage = 0; stage < 3; stage++) {
        const int m = 1 << stage;        // xor mask: 1, 2, 4
        const int h = 4 >> stage;        // surviving half-size: 4, 2, 1
        const bool up = (lane & m) != 0;
        #pragma unroll
        for (int r = 0; r < h; r++) {
            const float x = up ? s[r + h] : s[r];
            const float y = up ? s[r]     : s[r + h];
            s[r] = x + __shfl_xor_sync(0xFFFFFFFFu, y, m);
        }
    }
    {
        float t = s[0];
        t += __shfl_xor_sync(0xFFFFFFFFu, t, 8);
        t += __shfl_xor_sync(0xFFFFFFFFu, t, 16);
        if (lane < 8) {
            const int row = ((lane & 1) << 2) | (lane & 2) | ((lane & 4) >> 2);
            wsum[row][wid] = t;
        }
    }
    __syncthreads();

    if (tid < ROWS) {
        float acc = 0.0f;
        #pragma unroll
        for (int w = 0; w < 8; w++) acc += wsum[tid][w];
        inv_s[tid] = __fdividef(1.0f, acc);
    }
    __syncthreads();

    float* __restrict__ ob =
        out + ((size_t)bq * K + row0) * K + (jb - base);

    #pragma unroll
    for (int r = 0; r < ROWS; r++) {
        const float inv = inv_s[r];
        const float4 res = make_float4(v0[r] * inv, v1[r] * inv,
                                       v2[r] * inv, v3[r] * inv);
        __stcs(reinterpret_cast<float4*>(ob + (size_t)r * K), res);  // STG.128.CS
    }
}

extern "C" void kernel_launch(void* const* d_in, const int* in_sizes, int n_in,
                              void* d_out, int out_size)
{
    const float* coords = (const float*)d_in[0];   // [128, 1024, 3] f32
    const float* prec   = (const float*)d_in[1];   // [1] f32
    float* out          = (float*)d_out;           // [128, 1024, 1024] f32

    prep_kernel<<<BK / 256, 256>>>(coords, prec);

    // Main kernel with programmatic dependent launch: its blocks may start
    // (and run the prologue) while prep drains; the device-side
    // cudaGridDependencySynchronize() gates the first scratch read.
    cudaLaunchConfig_t cfg = {};
    cfg.gridDim  = dim3(B * (K / ROWS));   // 16384 blocks
    cfg.blockDim = dim3(THREADS);
    cudaLaunchAttribute attrs[1];
    attrs[0].id = cudaLaunchAttributeProgrammaticStreamSerialization;
    attrs[0].val.programmaticStreamSerializationAllowed = 1;
    cfg.attrs    = attrs;
    cfg.numAttrs = 1;

    cudaError_t err = cudaLaunchKernelEx(&cfg, adjacency_softmax_kernel, out);
    if (err != cudaSuccess) {
        // Fallback: plain serial launch (identical semantics, no overlap).
        adjacency_softmax_kernel<<<B * (K / ROWS), THREADS>>>(out);
    }
}